// round 17
// baseline (speedup 1.0000x reference)
#include <cuda_runtime.h>
#include <cuda_bf16.h>
#include <cuda_fp16.h>
#include <cstdint>

#define D_ 6
#define N_ 32768
#define K_ 16
#define DIN_ 64
#define DOUT_ 64
#define V_ 100000

typedef unsigned long long u64;

// Interleaved ping-pong state, 16B per (row, dim-pair):
//   word0 (u64): c as f32x2
//   word1 (u64): low u32 = h as f16x2, high u32 = G(=0.5*h@Uf) as f16x2
// Row 0 = zero row for masked children: .bss zero, never written.
__device__ u64 g_st[2][(N_ + 1) * 64];
// Pre-swizzled f16 weight planes: UA[6144] | UF[2048] | WW[8192]  (u32 words)
__device__ uint32_t g_Wpl[16384];
// E pre-converted to f16x2: [V][32 u32]
__device__ uint32_t g_Ef16[(size_t)V_ * 32];
// software grid barrier
__device__ unsigned g_cnt;
__device__ unsigned g_gen;

#define HALF2 0x3F0000003F000000ULL   // {0.5f, 0.5f} f32x2
#define HHALF2 0x38003800u            // {0.5, 0.5} f16x2

__device__ __forceinline__ u64 pk2(float lo, float hi) {
    u64 r; asm("mov.b64 %0, {%1,%2};" : "=l"(r) : "f"(lo), "f"(hi)); return r;
}
__device__ __forceinline__ void upk2(u64 v, float& lo, float& hi) {
    asm("mov.b64 {%0,%1}, %2;" : "=f"(lo), "=f"(hi) : "l"(v));
}
__device__ __forceinline__ u64 fma2_(u64 a, u64 b, u64 c) {
    u64 d; asm("fma.rn.f32x2 %0, %1, %2, %3;" : "=l"(d) : "l"(a), "l"(b), "l"(c)); return d;
}
__device__ __forceinline__ u64 add2_(u64 a, u64 b) {
    u64 d; asm("add.rn.f32x2 %0, %1, %2;" : "=l"(d) : "l"(a), "l"(b)); return d;
}
__device__ __forceinline__ u64 mul2_(u64 a, u64 b) {
    u64 d; asm("mul.rn.f32x2 %0, %1, %2;" : "=l"(d) : "l"(a), "l"(b)); return d;
}
__device__ __forceinline__ float tanha(float x) {
    float y; asm("tanh.approx.f32 %0, %1;" : "=f"(y) : "f"(x)); return y;
}
__device__ __forceinline__ u64 sig2h(u64 argHalf) {   // sigmoid(2*arg), f32 path (gates)
    float a, b; upk2(argHalf, a, b);
    return fma2_(pk2(tanha(a), tanha(b)), HALF2, HALF2);
}
__device__ __forceinline__ u64 tanh2(u64 v) {
    float a, b; upk2(v, a, b);
    return pk2(tanha(a), tanha(b));
}
// f16x2 ops for the per-child forget gate
__device__ __forceinline__ uint32_t hadd2_(uint32_t a, uint32_t b) {
    uint32_t d; asm("add.f16x2 %0, %1, %2;" : "=r"(d) : "r"(a), "r"(b)); return d;
}
__device__ __forceinline__ uint32_t htanh2(uint32_t a) {
    uint32_t d; asm("tanh.approx.f16x2 %0, %1;" : "=r"(d) : "r"(a)); return d;
}
__device__ __forceinline__ uint32_t hfma2h(uint32_t a, uint32_t b, uint32_t c) {
    uint32_t d; asm("fma.rn.f16x2 %0, %1, %2, %3;" : "=r"(d) : "r"(a), "r"(b), "r"(c)); return d;
}
__device__ __forceinline__ uint32_t smem_u32(const void* p) {
    uint32_t a;
    asm("{ .reg .u64 t; cvta.to.shared.u64 t, %1; cvt.u32.u64 %0, t; }" : "=r"(a) : "l"(p));
    return a;
}
__device__ __forceinline__ uint32_t h2pk(float lo, float hi) {
    __half2 h = __float22half2_rn(make_float2(lo, hi));
    return *reinterpret_cast<uint32_t*>(&h);
}
__device__ __forceinline__ u64 h2up(uint32_t v) {   // f16x2 -> f32x2 (u64)
    __half2 h = *reinterpret_cast<__half2*>(&v);
    float2 f = __half22float2(h);
    return pk2(f.x, f.y);
}
#define SW128(off) ((off) ^ (((off) >> 3) & 0x70))

__device__ __forceinline__ void ldm_x4(uint32_t* r, uint32_t addr) {
    asm volatile("ldmatrix.sync.aligned.m8n8.x4.shared.b16 {%0,%1,%2,%3}, [%4];"
                 : "=r"(r[0]), "=r"(r[1]), "=r"(r[2]), "=r"(r[3]) : "r"(addr));
}
__device__ __forceinline__ void mma16816h(float* c, const uint32_t* a,
                                          uint32_t b0, uint32_t b1) {
    asm volatile(
        "mma.sync.aligned.m16n8k16.row.col.f32.f16.f16.f32 "
        "{%0,%1,%2,%3}, {%4,%5,%6,%7}, {%8,%9}, {%0,%1,%2,%3};"
        : "+f"(c[0]), "+f"(c[1]), "+f"(c[2]), "+f"(c[3])
        : "r"(a[0]), "r"(a[1]), "r"(a[2]), "r"(a[3]), "r"(b0), "r"(b1));
}

// ============ prep: weight planes, E->f16, barrier reset ========================
__global__ void prep_kernel(const float* __restrict__ Uf,
                            const float* __restrict__ Uiuo,
                            const float* __restrict__ Ww,
                            const float* __restrict__ E) {
    if (blockIdx.x == 0 && threadIdx.x == 0) { g_cnt = 0u; g_gen = 0u; }
    const int gid = blockIdx.x * 256 + threadIdx.x;
    for (int i = gid; i < V_ * 32; i += 256 * 256) {
        float2 v = __ldg(reinterpret_cast<const float2*>(E) + i);
        g_Ef16[i] = h2pk(v.x, v.y);
    }
    if (blockIdx.x < 8) {
        int idx0 = blockIdx.x * 256 + threadIdx.x;
        for (int idx = idx0; idx < 16384; idx += 2048) {
            if (idx < 6144) {
                int n = idx >> 5, kp = idx & 31;
                uint32_t off = SW128((uint32_t)(n * 128 + kp * 4)) >> 2;
                g_Wpl[off] = h2pk(Uiuo[(2 * kp) * 192 + n],
                                  Uiuo[(2 * kp + 1) * 192 + n]);
            } else if (idx < 8192) {
                int i2 = idx - 6144;
                int n = i2 >> 5, kp = i2 & 31;
                uint32_t off = SW128((uint32_t)(n * 128 + kp * 4)) >> 2;
                g_Wpl[6144 + off] = h2pk(0.5f * Uf[(2 * kp) * 64 + n],
                                         0.5f * Uf[(2 * kp + 1) * 64 + n]);
            } else {
                int i2 = idx - 8192;
                int n = i2 >> 5, kp = i2 & 31;
                uint32_t off = SW128((uint32_t)(n * 128 + kp * 4)) >> 2;
                g_Wpl[8192 + off] = h2pk(Ww[(2 * kp) * 256 + n],
                                         Ww[(2 * kp + 1) * 256 + n]);
            }
        }
    }
}

// ========== single persistent kernel: Wx + gather + LSTM, all 6 depths ===========
#define UA_F 0
#define UF_F 24576
#define WW_F 32768
#define XE_F 65536         // tile A embeddings f16 [64r][64k] swizzled
#define XE2_F 73728        // tile B embeddings
#define AS_F 81920         // hs / new_h f16 staging
#define FS_F 90112         // f-gate: 0.5*(Wx_f + b_f) f16x2, [64r][33 u32] padded
#define BF_F 98560         // branch_f f16, [64r][33 u32] padded
#define LB_F 107008        // 128 labels
#define NODE_SMEM 107520
#define NODE_GRID 256

__global__ __launch_bounds__(256, 2) void node_all_kernel(const int* __restrict__ labels,
                                                          const int* __restrict__ child_idx,
                                                          const float* __restrict__ Wb,
                                                          float* __restrict__ out) {
    extern __shared__ char smc[];
    const uint32_t sb = smem_u32(smc);
    const int tid = threadIdx.x, lane = tid & 31, w = tid >> 5;

    const unsigned gen0 = *((volatile unsigned*)&g_gen);

    // stage all f16 weight planes ONCE per CTA (persist across depths)
    for (int i = tid; i < 4096; i += 256)
        reinterpret_cast<uint4*>(smc)[i] = __ldg(reinterpret_cast<const uint4*>(g_Wpl) + i);

    uint32_t* FS32 = reinterpret_cast<uint32_t*>(smc + FS_F);
    uint32_t* BF32 = reinterpret_cast<uint32_t*>(smc + BF_F);
    int* LBi = reinterpret_cast<int*>(smc + LB_F);
    const int g = lane >> 2, q = lane & 3;
    const int mrow = 16 * (w & 3), cg = w >> 2;
    const int lrow = ((lane >> 3) & 1) * 8 + (lane & 7);
    const int lkb  = (lane >> 4) * 16;
    const int nb0 = blockIdx.x * 128;

    // ---- depth-0 XE staging (both tiles) ----
    if (tid < 128) LBi[tid] = labels[nb0 + tid];
    __syncthreads();
#pragma unroll
    for (int i = 0; i < 4; i++) {
        int linear = i * 256 + tid;
        int r = linear >> 3, f = linear & 7;
        uint4 v = __ldg(reinterpret_cast<const uint4*>(
                            g_Ef16 + (size_t)LBi[r] * 32) + f);
        uint32_t base = (r < 64) ? XE_F : XE2_F;
        *reinterpret_cast<uint4*>(smc + base +
                                  SW128((uint32_t)((r & 63) * 128 + f * 16))) = v;
    }
    __syncthreads();

    for (int depth = 0; depth < D_; depth++) {
        const int rb = depth & 1;
        const u64* __restrict__ sp = g_st[rb];
        u64* __restrict__ sn = g_st[rb ^ 1];
        const size_t dN = (size_t)depth * N_;
        const bool last = (depth == D_ - 1);
        const char* spb_l = reinterpret_cast<const char*>(sp) + lane * 16;

        // ---- prefetch child indices for BOTH tiles, pre-scaled to byte offsets
        uint32_t ci[2][2][1];
        int ciT[2][2];  // [tile][iterhalf]: raw
        uint32_t cs00 = 0, cs01 = 0, cs10 = 0, cs11 = 0;
        if (depth != 0) {
            const size_t r0 = (dN + nb0 + 4 * w) * K_;
            cs00 = (uint32_t)child_idx[r0 + lane] << 9;
            cs01 = (uint32_t)child_idx[r0 + 32 * K_ + lane - 0 + 32] << 9;
            // fix: iter1 nodes are nb0+32+4w -> offset (32)*K_ from r0
        }
        // (clean recompute below to avoid confusion)
        uint32_t csv[2][2][2];   // [tile][iter][half]
        if (depth != 0) {
#pragma unroll
            for (int t2 = 0; t2 < 2; t2++) {
#pragma unroll
                for (int it = 0; it < 2; it++) {
                    const size_t cbase = (dN + nb0 + t2 * 64 + 32 * it + 4 * w) * K_;
                    csv[t2][it][0] = (uint32_t)child_idx[cbase + lane] << 9;
                    csv[t2][it][1] = (uint32_t)child_idx[cbase + 32 + lane] << 9;
                }
            }
        }
        (void)ci; (void)ciT; (void)cs00; (void)cs01; (void)cs10; (void)cs11;

        for (int ts = 0; ts < 2; ts++) {
            if (ts) __syncthreads();   // AS/FS/BF reuse hazard across tiles
            const int nb = nb0 + ts * 64;
            const uint32_t XEc = sb + (ts ? XE2_F : XE_F);

            // ========== phase 0b: f-block Wx = E @ Wf + b_f (pre-halved -> FS) ======
            if (depth != 0) {
                float af[4][4];
#pragma unroll
                for (int j4 = 0; j4 < 4; j4++)
#pragma unroll
                    for (int e = 0; e < 4; e++) af[j4][e] = 0.f;
#pragma unroll
                for (int kc = 0; kc < 4; kc++) {
                    const int koff = kc * 32 + lkb;
                    uint32_t a[4];
                    ldm_x4(a, XEc + SW128((uint32_t)((mrow + lrow) * 128 + koff)));
#pragma unroll
                    for (int tp = 0; tp < 2; tp++) {
                        int nrow = cg * 32 + tp * 16 + lrow;   // WW rows 0..63 = f
                        uint32_t bb[4];
                        ldm_x4(bb, sb + WW_F + SW128((uint32_t)(nrow * 128 + koff)));
                        mma16816h(af[2 * tp],     a, bb[0], bb[2]);
                        mma16816h(af[2 * tp + 1], a, bb[1], bb[3]);
                    }
                }
#pragma unroll
                for (int j4 = 0; j4 < 4; j4++) {
                    const int dp = 16 * cg + 4 * j4 + q;
                    float2 bia = __ldg(reinterpret_cast<const float2*>(Wb + 2 * dp));
#pragma unroll
                    for (int rh = 0; rh < 2; rh++) {
                        const int r = mrow + 8 * rh + g;
                        FS32[r * 33 + dp] = h2pk(0.5f * (af[j4][2 * rh] + bia.x),
                                                 0.5f * (af[j4][2 * rh + 1] + bia.y));
                    }
                }
                __syncthreads();   // FS ready for gather

                // ========== phase 1: gather children, f-gate in f16x2 ===============
#pragma unroll
                for (int iter = 0; iter < 2; iter++) {
                    const int rl0 = 32 * iter + 4 * w;
                    uint32_t c0 = csv[ts][iter][0];
                    uint32_t c1 = csv[ts][iter][1];
                    uint32_t wf16[4];
                    u64 hs[4] = {0, 0, 0, 0}, bfa[4] = {0, 0, 0, 0};
#pragma unroll
                    for (int q4 = 0; q4 < 4; q4++)
                        wf16[q4] = FS32[(rl0 + q4) * 33 + lane];
#pragma unroll 4
                    for (int k = 0; k < K_; k++) {
#pragma unroll
                        for (int q4 = 0; q4 < 4; q4++) {
                            int sl = q4 * 16 + k;
                            uint32_t cs = (sl < 32)
                                ? __shfl_sync(0xffffffffu, c0, sl)
                                : __shfl_sync(0xffffffffu, c1, sl - 32);
                            ulonglong2 s = __ldg(reinterpret_cast<const ulonglong2*>(
                                                     spb_l + cs));
                            uint32_t Gh = (uint32_t)(s.y >> 32);
                            uint32_t sg = hfma2h(htanh2(hadd2_(wf16[q4], Gh)),
                                                 HHALF2, HHALF2);
                            hs[q4] = add2_(hs[q4], h2up((uint32_t)s.y));
                            bfa[q4] = fma2_(s.x, h2up(sg), bfa[q4]);
                        }
                    }
#pragma unroll
                    for (int q4 = 0; q4 < 4; q4++) {
                        int r = rl0 + q4;
                        float xl, xh; upk2(hs[q4], xl, xh);
                        *reinterpret_cast<uint32_t*>(
                            smc + AS_F + SW128((uint32_t)(r * 128 + 4 * lane)))
                            = h2pk(xl, xh);
                        float bl, bh; upk2(bfa[q4], bl, bh);
                        BF32[r * 33 + lane] = h2pk(bl, bh);
                    }
                }
                __syncthreads();
            }

            // ========== phase 2: iuo = E@W_iuo (+ hs@U_iuo if depth>0) =============
            float acc[3][4][4];
#pragma unroll
            for (int b = 0; b < 3; b++)
#pragma unroll
                for (int j4 = 0; j4 < 4; j4++)
#pragma unroll
                    for (int e = 0; e < 4; e++) acc[b][j4][e] = 0.f;

#pragma unroll
            for (int kc = 0; kc < 4; kc++) {
                const int koff = kc * 32 + lkb;
                uint32_t a[4];
                ldm_x4(a, XEc + SW128((uint32_t)((mrow + lrow) * 128 + koff)));
#pragma unroll
                for (int b = 0; b < 3; b++)
#pragma unroll
                    for (int tp = 0; tp < 2; tp++) {
                        int nrow = (b + 1) * 64 + cg * 32 + tp * 16 + lrow;
                        uint32_t bb[4];
                        ldm_x4(bb, sb + WW_F + SW128((uint32_t)(nrow * 128 + koff)));
                        mma16816h(acc[b][2 * tp],     a, bb[0], bb[2]);
                        mma16816h(acc[b][2 * tp + 1], a, bb[1], bb[3]);
                    }
            }
            if (depth != 0) {
#pragma unroll
                for (int kc = 0; kc < 4; kc++) {
                    const int koff = kc * 32 + lkb;
                    uint32_t a[4];
                    ldm_x4(a, sb + AS_F + SW128((uint32_t)((mrow + lrow) * 128 + koff)));
#pragma unroll
                    for (int b = 0; b < 3; b++)
#pragma unroll
                        for (int tp = 0; tp < 2; tp++) {
                            int nrow = b * 64 + cg * 32 + tp * 16 + lrow;
                            uint32_t bb[4];
                            ldm_x4(bb, sb + UA_F + SW128((uint32_t)(nrow * 128 + koff)));
                            mma16816h(acc[b][2 * tp],     a, bb[0], bb[2]);
                            mma16816h(acc[b][2 * tp + 1], a, bb[1], bb[3]);
                        }
                }
            }

            // ========== phase 3: gates ==============================================
            u64 nhv[4][2], ncvv[4][2];
#pragma unroll
            for (int j4 = 0; j4 < 4; j4++) {
                const int dp = 16 * cg + 4 * j4 + q;
                float2 bi = __ldg(reinterpret_cast<const float2*>(Wb + 64 + 2 * dp));
                float2 bu = __ldg(reinterpret_cast<const float2*>(Wb + 128 + 2 * dp));
                float2 bo = __ldg(reinterpret_cast<const float2*>(Wb + 192 + 2 * dp));
                u64 bi2 = pk2(bi.x, bi.y), bu2 = pk2(bu.x, bu.y), bo2 = pk2(bo.x, bo.y);
#pragma unroll
                for (int rh = 0; rh < 2; rh++) {
                    const int r = mrow + 8 * rh + g;
                    u64 ai = pk2(acc[0][j4][2 * rh], acc[0][j4][2 * rh + 1]);
                    u64 au = pk2(acc[1][j4][2 * rh], acc[1][j4][2 * rh + 1]);
                    u64 ao = pk2(acc[2][j4][2 * rh], acc[2][j4][2 * rh + 1]);
                    u64 ig = sig2h(mul2_(add2_(ai, bi2), HALF2));
                    u64 ug = tanh2(add2_(au, bu2));
                    u64 og = sig2h(mul2_(add2_(ao, bo2), HALF2));
                    u64 bfv = (depth != 0) ? h2up(BF32[r * 33 + dp]) : 0ULL;
                    u64 ncv = fma2_(ig, ug, bfv);
                    u64 nh = mul2_(og, tanh2(ncv));
                    nhv[j4][rh] = nh;
                    ncvv[j4][rh] = ncv;
                    if (last)
                        reinterpret_cast<u64*>(out)[(size_t)(nb + r) * 32 + dp] = nh;
                }
            }

            if (!last) {
                // ========== phase 4: stage new_h, G = 0.5*(new_h @ U_f) =============
                __syncthreads();
#pragma unroll
                for (int j4 = 0; j4 < 4; j4++) {
                    const int dp = 16 * cg + 4 * j4 + q;
#pragma unroll
                    for (int rh = 0; rh < 2; rh++) {
                        const int r = mrow + 8 * rh + g;
                        float xl, xh; upk2(nhv[j4][rh], xl, xh);
                        *reinterpret_cast<uint32_t*>(
                            smc + AS_F + SW128((uint32_t)(r * 128 + 4 * dp)))
                            = h2pk(xl, xh);
                    }
                }
                __syncthreads();

                float ga[4][4];
#pragma unroll
                for (int t2 = 0; t2 < 4; t2++)
#pragma unroll
                    for (int e = 0; e < 4; e++) ga[t2][e] = 0.f;

#pragma unroll
                for (int kc = 0; kc < 4; kc++) {
                    const int koff = kc * 32 + lkb;
                    uint32_t a[4];
                    ldm_x4(a, sb + AS_F + SW128((uint32_t)((mrow + lrow) * 128 + koff)));
#pragma unroll
                    for (int tp = 0; tp < 2; tp++) {
                        int nrow = cg * 32 + tp * 16 + lrow;
                        uint32_t bb[4];
                        ldm_x4(bb, sb + UF_F + SW128((uint32_t)(nrow * 128 + koff)));
                        mma16816h(ga[2 * tp],     a, bb[0], bb[2]);
                        mma16816h(ga[2 * tp + 1], a, bb[1], bb[3]);
                    }
                }
                // combined STG.128 state store: {c f32x2, h|G f16x2}
#pragma unroll
                for (int tg = 0; tg < 4; tg++) {
                    const int dp = 16 * cg + 4 * tg + q;
#pragma unroll
                    for (int rh = 0; rh < 2; rh++) {
                        const int r = mrow + 8 * rh + g;
                        float xl, xh; upk2(nhv[tg][rh], xl, xh);
                        uint32_t hu = h2pk(xl, xh);
                        uint32_t gu = h2pk(ga[tg][2 * rh], ga[tg][2 * rh + 1]);
                        reinterpret_cast<ulonglong2*>(sn)[(size_t)(nb + r + 1) * 32 + dp]
                            = make_ulonglong2(ncvv[tg][rh], ((u64)gu << 32) | hu);
                    }
                }
            }
        }

        // ========== pipelined staging of NEXT depth's labels + XE (pre-barrier) ====
        if (!last) {
            __syncthreads();   // all warps past phase2 reads of XE buffers
            if (tid < 128) LBi[tid] = labels[(depth + 1) * N_ + nb0 + tid];
            __syncthreads();
#pragma unroll
            for (int i = 0; i < 4; i++) {
                int linear = i * 256 + tid;
                int r = linear >> 3, f = linear & 7;
                uint4 v = __ldg(reinterpret_cast<const uint4*>(
                                    g_Ef16 + (size_t)LBi[r] * 32) + f);
                uint32_t base = (r < 64) ? XE_F : XE2_F;
                *reinterpret_cast<uint4*>(smc + base +
                                          SW128((uint32_t)((r & 63) * 128 + f * 16))) = v;
            }

            // ================= grid barrier between depths =================
            __syncthreads();
            if (tid == 0) {
                __threadfence();
                unsigned a = atomicAdd(&g_cnt, 1u);
                unsigned target = gen0 + (unsigned)depth + 1u;
                if ((a % NODE_GRID) == NODE_GRID - 1) {
                    atomicAdd(&g_gen, 1u);
                } else {
                    while (*((volatile unsigned*)&g_gen) < target) {}
                }
                __threadfence();
            }
            __syncthreads();
        }
    }
}

extern "C" void kernel_launch(void* const* d_in, const int* in_sizes, int n_in,
                              void* d_out, int out_size) {
    const int*   labels    = (const int*)d_in[0];
    const int*   child_idx = (const int*)d_in[1];
    const float* E         = (const float*)d_in[2];
    const float* Ww        = (const float*)d_in[3];
    const float* Wb        = (const float*)d_in[4];
    const float* Uf        = (const float*)d_in[5];
    const float* Uiuo      = (const float*)d_in[6];
    float*       out       = (float*)d_out;

    cudaFuncSetAttribute(node_all_kernel, cudaFuncAttributeMaxDynamicSharedMemorySize,
                         NODE_SMEM);

    prep_kernel<<<256, 256>>>(Uf, Uiuo, Ww, E);
    node_all_kernel<<<NODE_GRID, 256, NODE_SMEM>>>(labels, child_idx, Wb, out);
}